// round 4
// baseline (speedup 1.0000x reference)
#include <cuda_runtime.h>
#include <cuda_fp16.h>
#include <math.h>

// NO __device__ globals, NO static-init CUDA calls, NO local arrays.
// All scratch is carved out of d_out (N*20 + N*32 floats = 20.8 MB):
//   [0      , 6.4MB)  X   : fp16 feature staging, N*32 halves (t1 / h1 / t2, reused)
//   [6.4MB  , 6.8MB)  dis : fp32 N      (1/sqrt(deg))
//   [6.8MB  , 7.2MB)  deg : int  N
//   [8.0MB  , 20.8MB) Y   : fp32 N*32   (atomic accumulator; finally holds h2 = output)
// The classifier writes [0, 8MB) last, when X/dis/deg are dead.

#define HID 32

// ---------------- degree ----------------
__global__ __launch_bounds__(256) void count_deg_kernel(const int* __restrict__ col,
                                                        int* __restrict__ deg, int e) {
    int i = blockIdx.x * blockDim.x + threadIdx.x;
    if (i < e) atomicAdd(&deg[col[i]], 1);
}

__global__ __launch_bounds__(256) void make_dis_kernel(const int* __restrict__ deg,
                                                       float* __restrict__ dis, int n) {
    int i = blockIdx.x * blockDim.x + threadIdx.x;
    if (i < n) {
        int d = deg[i];
        dis[i] = (d > 0) ? rsqrtf((float)d) : 0.0f;
    }
}

// ---------------- GEMM1: X[n][j] = fp16( dis[n] * sum_k x[n][k]*W1[k][j] ) ----------------
// Warp per node. W1 transposed into padded shared memory (conflict-free float4).
__global__ __launch_bounds__(256) void gemm1_kernel(const float* __restrict__ A,
                                                    const float* __restrict__ W,
                                                    const float* __restrict__ dis,
                                                    __half* __restrict__ X, int n_nodes) {
    const int K = 128;
    __shared__ __align__(16) float Wt[HID][K + 4];
    __shared__ __align__(16) float xs[8][K];

    for (int i = threadIdx.x; i < K * HID; i += blockDim.x) {
        int k = i >> 5, j = i & 31;
        Wt[j][k] = W[i];
    }
    __syncthreads();

    int warp = threadIdx.x >> 5, lane = threadIdx.x & 31;
    int n = blockIdx.x * 8 + warp;
    if (n >= n_nodes) return;

    const float4* xr = (const float4*)(A + (long)n * K);
    float4* xsr = (float4*)&xs[warp][0];
    for (int i = lane; i < K / 4; i += 32) xsr[i] = xr[i];
    __syncwarp();

    const float4* wr = (const float4*)&Wt[lane][0];
    float acc = 0.0f;
#pragma unroll
    for (int k4 = 0; k4 < K / 4; k4++) {
        float4 w = wr[k4];
        float4 xx = xsr[k4];
        acc = fmaf(w.x, xx.x, acc);
        acc = fmaf(w.y, xx.y, acc);
        acc = fmaf(w.z, xx.z, acc);
        acc = fmaf(w.w, xx.w, acc);
    }
    X[n * HID + lane] = __float2half_rn(acc * dis[n]);
}

// ---------------- GEMM2 (in place): X[n][:] <- fp16( dis[n] * (h1[n][:] @ W2) ) ----------------
__global__ __launch_bounds__(256) void gemm2_kernel(const float* __restrict__ W,
                                                    const float* __restrict__ dis,
                                                    __half* __restrict__ X, int n_nodes) {
    const int K = HID;
    __shared__ __align__(16) float Wt[HID][K + 4];   // Wt[j][k] = W2[k][j]
    __shared__ float hs[8][K];

    for (int i = threadIdx.x; i < K * HID; i += blockDim.x) {
        int k = i >> 5, j = i & 31;
        Wt[j][k] = W[i];
    }
    __syncthreads();

    int warp = threadIdx.x >> 5, lane = threadIdx.x & 31;
    int n = blockIdx.x * 8 + warp;
    if (n >= n_nodes) return;

    hs[warp][lane] = __half2float(X[n * HID + lane]);
    __syncwarp();

    float acc = 0.0f;
#pragma unroll
    for (int k = 0; k < K; k++) acc = fmaf(hs[warp][k], Wt[lane][k], acc);

    __syncwarp();  // all reads into hs done before in-place write
    X[n * HID + lane] = __float2half_rn(acc * dis[n]);
}

// ---------------- aggregation: edge-parallel push, vector fp32 reduction ----------------
// 4 edges per warp; 8 lanes per edge; each lane handles 4 features (one red.v4.f32).
__global__ __launch_bounds__(256) void agg_push_kernel(const __half* __restrict__ X,
                                                       const int* __restrict__ row,
                                                       const int* __restrict__ col,
                                                       float* __restrict__ Y, int e) {
    int gw  = (blockIdx.x * blockDim.x + threadIdx.x) >> 5;
    int lane = threadIdx.x & 31;
    int eb   = gw * 4 + (lane >> 3);
    int quad = lane & 7;
    if (eb >= e) return;

    int src = __ldg(&row[eb]);
    int dst = __ldg(&col[eb]);

    const __half2* p = (const __half2*)(X + src * HID) + quad * 2;  // 8B aligned
    __half2 h0 = __ldg(&p[0]);
    __half2 h1 = __ldg(&p[1]);
    float2 f0 = __half22float2(h0);
    float2 f1 = __half22float2(h1);

    float* yp = Y + dst * HID + quad * 4;  // 16B aligned
    asm volatile("red.global.add.v4.f32 [%0], {%1, %2, %3, %4};"
                 :: "l"(yp), "f"(f0.x), "f"(f0.y), "f"(f1.x), "f"(f1.y)
                 : "memory");
}

// ---------------- activation epilogues ----------------
// act1: h1 = tanh(dis[n]*Y + b1) -> X (fp16, in place over t1); re-zero Y for layer 2.
__global__ __launch_bounds__(256) void act1_kernel(float* __restrict__ Y,
                                                   const float* __restrict__ dis,
                                                   const float* __restrict__ b,
                                                   __half* __restrict__ X, int n_nodes) {
    int idx = blockIdx.x * blockDim.x + threadIdx.x;
    if (idx >= n_nodes * HID) return;
    int node = idx >> 5, j = idx & 31;
    float v = tanhf(dis[node] * Y[idx] + __ldg(&b[j]));
    X[idx] = __float2half_rn(v);
    Y[idx] = 0.0f;
}

// act2: h2 = tanh(dis[n]*Y + b2) -> Y in place (Y IS the h output region).
__global__ __launch_bounds__(256) void act2_kernel(float* __restrict__ Y,
                                                   const float* __restrict__ dis,
                                                   const float* __restrict__ b, int n_nodes) {
    int idx = blockIdx.x * blockDim.x + threadIdx.x;
    if (idx >= n_nodes * HID) return;
    int node = idx >> 5, j = idx & 31;
    Y[idx] = tanhf(dis[node] * Y[idx] + __ldg(&b[j]));
}

// ---------------- classifier: logits + log_softmax, warp per node ----------------
__global__ __launch_bounds__(256) void cls_kernel(const float* __restrict__ h,
                                                  const float* __restrict__ Wc,
                                                  const float* __restrict__ bc,
                                                  float* __restrict__ out, int n_nodes) {
    const int OUT = 20;
    __shared__ float Wcs[HID * OUT];
    __shared__ float hs[8][HID];

    for (int i = threadIdx.x; i < HID * OUT; i += blockDim.x) Wcs[i] = Wc[i];
    __syncthreads();

    int warp = threadIdx.x >> 5, lane = threadIdx.x & 31;
    int n = blockIdx.x * 8 + warp;
    if (n >= n_nodes) return;

    hs[warp][lane] = h[n * HID + lane];
    __syncwarp();

    float z = -INFINITY;
    if (lane < OUT) {
        float acc = bc[lane];
#pragma unroll
        for (int k = 0; k < HID; k++)
            acc = fmaf(hs[warp][k], Wcs[k * OUT + lane], acc);
        z = acc;
    }
    float m = z;
#pragma unroll
    for (int off = 16; off; off >>= 1)
        m = fmaxf(m, __shfl_xor_sync(0xffffffff, m, off));
    float ev = (lane < OUT) ? expf(z - m) : 0.0f;
    float s = ev;
#pragma unroll
    for (int off = 16; off; off >>= 1)
        s += __shfl_xor_sync(0xffffffff, s, off);
    if (lane < OUT) out[n * OUT + lane] = z - m - logf(s);
}

// ---------------- launch ----------------
extern "C" void kernel_launch(void* const* d_in, const int* in_sizes, int n_in,
                              void* d_out, int out_size) {
    const float* x  = (const float*)d_in[0];
    const int*   ei = (const int*)d_in[1];
    const float* W1 = (const float*)d_in[2];
    const float* b1 = (const float*)d_in[3];
    const float* W2 = (const float*)d_in[4];
    const float* b2 = (const float*)d_in[5];
    const float* Wc = (const float*)d_in[6];
    const float* bc = (const float*)d_in[7];

    const int n = in_sizes[0] / 128;   // 100000
    const int e = in_sizes[1] / 2;     // 3200000
    const int* row = ei;
    const int* col = ei + e;

    // Scratch carved from d_out (see map at top of file).
    float*  outp = (float*)d_out;                               // final [n,20]
    float*  Y    = outp + (long)n * 20;                         // [n,32] accumulator -> h2
    __half* X    = (__half*)d_out;                              // [n,32] fp16 staging
    float*  dis  = (float*)((char*)d_out + (long)n * HID * 2);  // n floats @ 6.4MB
    int*    deg  = (int*)((char*)dis + (long)n * 4);            // n ints   @ 6.8MB

    const int TB = 256;
    int gN  = (n + TB - 1) / TB;
    int gE  = (e + TB - 1) / TB;
    int gW  = (n + 7) / 8;                       // warp-per-node grids
    int gNE = (n * HID + TB - 1) / TB;           // elementwise grids
    int gA  = (e + 31) / 32;                     // 32 edges per 256-thread block

    cudaMemsetAsync(deg, 0, (size_t)n * 4);
    cudaMemsetAsync(Y, 0, (size_t)n * HID * 4);

    count_deg_kernel<<<gE, TB>>>(col, deg, e);
    make_dis_kernel<<<gN, TB>>>(deg, dis, n);

    // Layer 1
    gemm1_kernel<<<gW, TB>>>(x, W1, dis, X, n);
    agg_push_kernel<<<gA, TB>>>(X, row, col, Y, e);
    act1_kernel<<<gNE, TB>>>(Y, dis, b1, X, n);          // h1 -> X, Y re-zeroed

    // Layer 2
    gemm2_kernel<<<gW, TB>>>(W2, dis, X, n);             // t2 -> X in place
    agg_push_kernel<<<gA, TB>>>(X, row, col, Y, e);
    act2_kernel<<<gNE, TB>>>(Y, dis, b2, n);             // h2 -> Y (= output h region)

    // Classifier + log_softmax (clobbers X/dis/deg region — all dead)
    cls_kernel<<<gW, TB>>>(Y, Wc, bc, outp, n);
}

// round 5
// speedup vs baseline: 1.0663x; 1.0663x over previous
#include <cuda_runtime.h>
#include <cuda_fp16.h>
#include <math.h>

// NO __device__ globals, NO static-init CUDA calls, NO local arrays.
// All scratch is carved out of d_out (N*20 + N*32 floats = 20.8 MB):
//   [0      , 6.4MB)  X   : fp16 feature staging, N*32 halves (t1 / h1 / t2, reused)
//   [6.4MB  , 6.8MB)  dis : fp32 N      (1/sqrt(deg))
//   [6.8MB  , 7.2MB)  deg : int  N
//   [8.0MB  , 20.8MB) Y   : fp32 N*32   (atomic accumulator; finally holds h2 = output)
// The classifier writes [0, 8MB) last, when X/dis/deg are dead.

#define HID 32

// ---------------- degree ----------------
__global__ __launch_bounds__(256) void count_deg_kernel(const int* __restrict__ col,
                                                        int* __restrict__ deg, int e) {
    int i = blockIdx.x * blockDim.x + threadIdx.x;
    if (i < e) atomicAdd(&deg[col[i]], 1);
}

__global__ __launch_bounds__(256) void make_dis_kernel(const int* __restrict__ deg,
                                                       float* __restrict__ dis, int n) {
    int i = blockIdx.x * blockDim.x + threadIdx.x;
    if (i < n) {
        int d = deg[i];
        dis[i] = (d > 0) ? rsqrtf((float)d) : 0.0f;
    }
}

// ---------------- GEMM1: X[n][j] = fp16( dis[n] * sum_k x[n][k]*W1[k][j] ) ----------------
__global__ __launch_bounds__(256) void gemm1_kernel(const float* __restrict__ A,
                                                    const float* __restrict__ W,
                                                    const float* __restrict__ dis,
                                                    __half* __restrict__ X, int n_nodes) {
    const int K = 128;
    __shared__ __align__(16) float Wt[HID][K + 4];
    __shared__ __align__(16) float xs[8][K];

    for (int i = threadIdx.x; i < K * HID; i += blockDim.x) {
        int k = i >> 5, j = i & 31;
        Wt[j][k] = W[i];
    }
    __syncthreads();

    int warp = threadIdx.x >> 5, lane = threadIdx.x & 31;
    int n = blockIdx.x * 8 + warp;
    if (n >= n_nodes) return;

    const float4* xr = (const float4*)(A + (long)n * K);
    float4* xsr = (float4*)&xs[warp][0];
    for (int i = lane; i < K / 4; i += 32) xsr[i] = xr[i];
    __syncwarp();

    const float4* wr = (const float4*)&Wt[lane][0];
    float acc = 0.0f;
#pragma unroll
    for (int k4 = 0; k4 < K / 4; k4++) {
        float4 w = wr[k4];
        float4 xx = xsr[k4];
        acc = fmaf(w.x, xx.x, acc);
        acc = fmaf(w.y, xx.y, acc);
        acc = fmaf(w.z, xx.z, acc);
        acc = fmaf(w.w, xx.w, acc);
    }
    X[n * HID + lane] = __float2half_rn(acc * dis[n]);
}

// ---------------- GEMM2 (in place): X[n][:] <- fp16( dis[n] * (h1[n][:] @ W2) ) ------------
__global__ __launch_bounds__(256) void gemm2_kernel(const float* __restrict__ W,
                                                    const float* __restrict__ dis,
                                                    __half* __restrict__ X, int n_nodes) {
    const int K = HID;
    __shared__ __align__(16) float Wt[HID][K + 4];
    __shared__ float hs[8][K];

    for (int i = threadIdx.x; i < K * HID; i += blockDim.x) {
        int k = i >> 5, j = i & 31;
        Wt[j][k] = W[i];
    }
    __syncthreads();

    int warp = threadIdx.x >> 5, lane = threadIdx.x & 31;
    int n = blockIdx.x * 8 + warp;
    if (n >= n_nodes) return;

    hs[warp][lane] = __half2float(X[n * HID + lane]);
    __syncwarp();

    float acc = 0.0f;
#pragma unroll
    for (int k = 0; k < K; k++) acc = fmaf(hs[warp][k], Wt[lane][k], acc);

    __syncwarp();
    X[n * HID + lane] = __float2half_rn(acc * dis[n]);
}

// ---------------- aggregation: edge-parallel push ----------------
// 16 edges per warp in 4 batched rounds (MLP ~8). Per round: 4 edges, 8 lanes
// per edge, each lane gathers 8B (uint2 = 4 halves) and issues one
// red.global.add.v4.f32 (16B fp32). Memory warp-instrs: 8 idx LDG + 4 LDG.64
// + 4 RED.128 per 16 edges = 1.0/edge (was 1.25/edge with MLP 2).
__global__ __launch_bounds__(256) void agg_push_kernel(const __half* __restrict__ X,
                                                       const int* __restrict__ row,
                                                       const int* __restrict__ col,
                                                       float* __restrict__ Y, int e) {
    const int R = 4;
    int gw   = (blockIdx.x * blockDim.x + threadIdx.x) >> 5;
    int lane = threadIdx.x & 31;
    int g    = lane >> 3;   // edge slot within round (0..3)
    int q    = lane & 7;    // feature quad (0..7)
    int base = gw * (4 * R);
    if (base >= e) return;

    int src[R], dst[R];
#pragma unroll
    for (int r = 0; r < R; r++) {
        int eb = base + r * 4 + g;
        bool ok = eb < e;
        src[r] = ok ? __ldg(&row[eb]) : 0;
        dst[r] = ok ? __ldg(&col[eb]) : -1;
    }

    uint2 v[R];
#pragma unroll
    for (int r = 0; r < R; r++)
        v[r] = __ldg((const uint2*)(X + src[r] * HID) + q);

#pragma unroll
    for (int r = 0; r < R; r++) {
        if (dst[r] >= 0) {
            __half2 h0 = *(__half2*)&v[r].x;
            __half2 h1 = *(__half2*)&v[r].y;
            float2 f0 = __half22float2(h0);
            float2 f1 = __half22float2(h1);
            float* yp = Y + dst[r] * HID + q * 4;
            asm volatile("red.global.add.v4.f32 [%0], {%1, %2, %3, %4};"
                         :: "l"(yp), "f"(f0.x), "f"(f0.y), "f"(f1.x), "f"(f1.y)
                         : "memory");
        }
    }
}

// ---------------- activation epilogues ----------------
__global__ __launch_bounds__(256) void act1_kernel(float* __restrict__ Y,
                                                   const float* __restrict__ dis,
                                                   const float* __restrict__ b,
                                                   __half* __restrict__ X, int n_nodes) {
    int idx = blockIdx.x * blockDim.x + threadIdx.x;
    if (idx >= n_nodes * HID) return;
    int node = idx >> 5, j = idx & 31;
    float v = tanhf(dis[node] * Y[idx] + __ldg(&b[j]));
    X[idx] = __float2half_rn(v);
    Y[idx] = 0.0f;
}

__global__ __launch_bounds__(256) void act2_kernel(float* __restrict__ Y,
                                                   const float* __restrict__ dis,
                                                   const float* __restrict__ b, int n_nodes) {
    int idx = blockIdx.x * blockDim.x + threadIdx.x;
    if (idx >= n_nodes * HID) return;
    int node = idx >> 5, j = idx & 31;
    Y[idx] = tanhf(dis[node] * Y[idx] + __ldg(&b[j]));
}

// ---------------- classifier: logits + log_softmax ----------------
__global__ __launch_bounds__(256) void cls_kernel(const float* __restrict__ h,
                                                  const float* __restrict__ Wc,
                                                  const float* __restrict__ bc,
                                                  float* __restrict__ out, int n_nodes) {
    const int OUT = 20;
    __shared__ float Wcs[HID * OUT];
    __shared__ float hs[8][HID];

    for (int i = threadIdx.x; i < HID * OUT; i += blockDim.x) Wcs[i] = Wc[i];
    __syncthreads();

    int warp = threadIdx.x >> 5, lane = threadIdx.x & 31;
    int n = blockIdx.x * 8 + warp;
    if (n >= n_nodes) return;

    hs[warp][lane] = h[n * HID + lane];
    __syncwarp();

    float z = -INFINITY;
    if (lane < OUT) {
        float acc = bc[lane];
#pragma unroll
        for (int k = 0; k < HID; k++)
            acc = fmaf(hs[warp][k], Wcs[k * OUT + lane], acc);
        z = acc;
    }
    float m = z;
#pragma unroll
    for (int off = 16; off; off >>= 1)
        m = fmaxf(m, __shfl_xor_sync(0xffffffff, m, off));
    float ev = (lane < OUT) ? expf(z - m) : 0.0f;
    float s = ev;
#pragma unroll
    for (int off = 16; off; off >>= 1)
        s += __shfl_xor_sync(0xffffffff, s, off);
    if (lane < OUT) out[n * OUT + lane] = z - m - logf(s);
}

// ---------------- launch ----------------
extern "C" void kernel_launch(void* const* d_in, const int* in_sizes, int n_in,
                              void* d_out, int out_size) {
    const float* x  = (const float*)d_in[0];
    const int*   ei = (const int*)d_in[1];
    const float* W1 = (const float*)d_in[2];
    const float* b1 = (const float*)d_in[3];
    const float* W2 = (const float*)d_in[4];
    const float* b2 = (const float*)d_in[5];
    const float* Wc = (const float*)d_in[6];
    const float* bc = (const float*)d_in[7];

    const int n = in_sizes[0] / 128;   // 100000
    const int e = in_sizes[1] / 2;     // 3200000
    const int* row = ei;
    const int* col = ei + e;

    float*  outp = (float*)d_out;                               // final [n,20]
    float*  Y    = outp + (long)n * 20;                         // [n,32] accumulator -> h2
    __half* X    = (__half*)d_out;                              // [n,32] fp16 staging
    float*  dis  = (float*)((char*)d_out + (long)n * HID * 2);  // n floats
    int*    deg  = (int*)((char*)dis + (long)n * 4);            // n ints

    const int TB = 256;
    int gN  = (n + TB - 1) / TB;
    int gE  = (e + TB - 1) / TB;
    int gW  = (n + 7) / 8;
    int gNE = (n * HID + TB - 1) / TB;
    int gA  = (e + 127) / 128;   // 8 warps/block x 16 edges/warp

    cudaMemsetAsync(deg, 0, (size_t)n * 4);
    cudaMemsetAsync(Y, 0, (size_t)n * HID * 4);

    count_deg_kernel<<<gE, TB>>>(col, deg, e);
    make_dis_kernel<<<gN, TB>>>(deg, dis, n);

    // Layer 1
    gemm1_kernel<<<gW, TB>>>(x, W1, dis, X, n);
    agg_push_kernel<<<gA, TB>>>(X, row, col, Y, e);
    act1_kernel<<<gNE, TB>>>(Y, dis, b1, X, n);          // h1 -> X, Y re-zeroed

    // Layer 2
    gemm2_kernel<<<gW, TB>>>(W2, dis, X, n);             // t2 -> X in place
    agg_push_kernel<<<gA, TB>>>(X, row, col, Y, e);
    act2_kernel<<<gNE, TB>>>(Y, dis, b2, n);             // h2 -> Y (= output h region)

    // Classifier + log_softmax
    cls_kernel<<<gW, TB>>>(Y, Wc, bc, outp, n);
}